// round 12
// baseline (speedup 1.0000x reference)
#include <cuda_runtime.h>
#include <cstdint>
#include <cstddef>

#define NN 50000
#define DD 256
#define EE 1000000
#define NB 196   // ceil(NN/256)

typedef unsigned long long u64;

// ---- device scratch (no malloc allowed) ----
__device__ float g_Y[2][NN][64];    // [m: 0=h,1=t][node][src-proj 64]
__device__ float g_a[2][NN][4];     // [m][node][ a_s h0, a_s h1, a_d h0, a_d h1 ]
__device__ float g_wv[4][DD];       // folded att vectors: [kind*2+h][k]
__device__ int   g_cnt[2][NN];      // in-degree histogram per direction
__device__ int   g_off[2][NN + 1];  // CSR offsets
__device__ int   g_cur[2][NN];      // scatter cursors
__device__ int   g_srcs[2][EE];     // edge sources sorted by dst
__device__ int   g_part[2][NB];     // per-block partials for scan
__device__ int   g_is64;            // edge_index dtype flag

__device__ __forceinline__ float elu1(float x) {
    return x > 0.f ? x : expm1f(x);
}

__device__ __forceinline__ u64 pack2(float lo, float hi) {
    u64 r; asm("mov.b64 %0, {%1,%2};" : "=l"(r) : "f"(lo), "f"(hi)); return r;
}
__device__ __forceinline__ void unpack2(u64 v, float& lo, float& hi) {
    asm("mov.b64 {%0,%1}, %2;" : "=f"(lo), "=f"(hi) : "l"(v));
}
__device__ __forceinline__ u64 ffma2(u64 a, u64 b, u64 c) {
    u64 d; asm("fma.rn.f32x2 %0, %1, %2, %3;" : "=l"(d) : "l"(a), "l"(b), "l"(c));
    return d;
}

// Detect int64 edge_index (odd 32-bit words all zero since values < 50000)
__global__ void detect_kernel(const int* __restrict__ ei32) {
    if (threadIdx.x == 0 && blockIdx.x == 0) {
        int z = ei32[1] | ei32[3] | ei32[5] | ei32[7] | ei32[9] | ei32[11] | ei32[13];
        g_is64 = (z == 0) ? 1 : 0;
        g_off[0][NN] = EE;
        g_off[1][NN] = EE;
    }
}

// fold attention vectors into W: g_wv[kind*2+h][k] = sum_c W[k][h*32+c]*att[h][c]
__global__ __launch_bounds__(256) void prep_wv_kernel(
    const float* __restrict__ Wsrc, const float* __restrict__ Wdst,
    const float* __restrict__ att_src, const float* __restrict__ att_dst)
{
    int idx = blockIdx.x * 256 + threadIdx.x;   // 0..1023
    if (idx >= 4 * DD) return;
    int q = idx >> 8;          // kind*2+h
    int k = idx & 255;
    int kind = q >> 1, h = q & 1;
    const float* W = kind ? Wdst : Wsrc;
    const float* att = kind ? att_dst : att_src;
    float s = 0.f;
    #pragma unroll
    for (int c = 0; c < 32; c++)
        s = fmaf(W[k * 64 + h * 32 + c], att[h * 32 + c], s);
    g_wv[q][k] = s;
}

__global__ void zero_kernel() {
    int i = blockIdx.x * blockDim.x + threadIdx.x;
    if (i < 2 * NN) ((int*)g_cnt)[i] = 0;
}

__device__ __forceinline__ void load_edge(const void* eiv, int e, int& a, int& b) {
    if (g_is64) {
        const long long* ei = (const long long*)eiv;
        a = (int)__ldg(&ei[e]); b = (int)__ldg(&ei[EE + e]);
    } else {
        const int* ei = (const int*)eiv;
        a = __ldg(&ei[e]); b = __ldg(&ei[EE + e]);
    }
}

// exclusive block scan helper (256 threads)
__device__ __forceinline__ int block_exscan(int v, int* tot) {
    int lane = threadIdx.x & 31, wid = threadIdx.x >> 5;
    int inc = v;
    #pragma unroll
    for (int o = 1; o < 32; o <<= 1) {
        int n = __shfl_up_sync(0xffffffffu, inc, o);
        if (lane >= o) inc += n;
    }
    __shared__ int ws[8];
    if (lane == 31) ws[wid] = inc;
    __syncthreads();
    if (wid == 0) {
        int w = (lane < 8) ? ws[lane] : 0;
        #pragma unroll
        for (int o = 1; o < 8; o <<= 1) {
            int n = __shfl_up_sync(0xffffffffu, w, o);
            if (lane >= o) w += n;
        }
        if (lane < 8) ws[lane] = w;
    }
    __syncthreads();
    int base = (wid > 0) ? ws[wid - 1] : 0;
    *tot = ws[7];
    return base + inc - v;
}

__global__ __launch_bounds__(256) void scan1_kernel() {
    int dir = blockIdx.y;
    int idx = blockIdx.x * 256 + threadIdx.x;
    int c = (idx < NN) ? g_cnt[dir][idx] : 0;
    int tot;
    block_exscan(c, &tot);
    if (threadIdx.x == 0) g_part[dir][blockIdx.x] = tot;
}

__global__ __launch_bounds__(256) void scan2_kernel() {
    int dir = blockIdx.x;
    int v = (threadIdx.x < NB) ? g_part[dir][threadIdx.x] : 0;
    int tot;
    int ex = block_exscan(v, &tot);
    if (threadIdx.x < NB) g_part[dir][threadIdx.x] = ex;
}

__global__ __launch_bounds__(256) void scan3_kernel() {
    int dir = blockIdx.y;
    int idx = blockIdx.x * 256 + threadIdx.x;
    int c = (idx < NN) ? g_cnt[dir][idx] : 0;
    int tot;
    int ex = block_exscan(c, &tot) + g_part[dir][blockIdx.x];
    if (idx < NN) {
        g_off[dir][idx] = ex;
        g_cur[dir][idx] = ex;
    }
}

__global__ __launch_bounds__(256) void scatter_kernel(const void* __restrict__ eiv) {
    int e = blockIdx.x * blockDim.x + threadIdx.x;
    if (e >= EE) return;
    int a, b;
    load_edge(eiv, e, a, b);
    int p0 = atomicAdd(&g_cur[0][b], 1);
    g_srcs[0][p0] = a;
    int p1 = atomicAdd(&g_cur[1][a], 1);
    g_srcs[1][p1] = b;
}

// Y[m] = elu(X_m) @ W_src (M=50000, N=64, K=256).
// Block tile 128x64, thread tile 8x4 (f32x2 row-pairs), DOUBLE-BUFFERED smem.
// Also: edge histogram slice issued as fire-and-forget REDs in the prologue,
// a_s from accumulators in the epilogue, a_d via packed smem loop.
__global__ __launch_bounds__(256, 2) void gemm_kernel(
    const float* __restrict__ hx, const float* __restrict__ txp,
    const float* __restrict__ Wsrc, const float* __restrict__ att_src,
    const void* __restrict__ eiv)
{
    const int m = blockIdx.y;
    const float* __restrict__ X = (m == 0) ? hx : txp;
    __shared__ __align__(16) float As[2][32][132];
    __shared__ float4 Bs[2][32][16];
    __shared__ float  Wch[2][2][32];
    const int tid = threadIdx.x;
    const int tcx = tid & 15, tcy = tid >> 4;
    const int row0 = blockIdx.x * 128;
    const int pair = tid & 63, aq = tid >> 6;   // a_d assignment (tid<128)

    // ---- histogram slice: fire-and-forget REDs, overlap with GEMM below ----
    {
        int bid = blockIdx.y * gridDim.x + blockIdx.x;   // 0..781
        int base = bid * 1280;
        #pragma unroll
        for (int t = 0; t < 5; t++) {
            int e = base + tid + t * 256;
            if (e < EE) {
                int a, b;
                load_edge(eiv, e, a, b);
                atomicAdd(&g_cnt[0][b], 1);
                atomicAdd(&g_cnt[1][a], 1);
            }
        }
    }

    u64 acc2[4][4];
    #pragma unroll
    for (int rp = 0; rp < 4; rp++)
        #pragma unroll
        for (int j = 0; j < 4; j++) acc2[rp][j] = 0ull;
    u64 sa2 = 0ull;

    // staging registers
    float4 va[4], vb[2];
    float wvr = 0.f;

    // addressing for staged loads
    const int ar = tid >> 3, ak4 = tid & 7;         // A: rows tid/8 (+32/it), k4
    const int bkk = tid >> 4, bj4 = tid & 15;       // B: kk (+16/it), j4

    #define LDG_CHUNK(k0)                                                        \
        {                                                                        \
            _Pragma("unroll")                                                    \
            for (int it = 0; it < 4; it++) {                                     \
                int grow = row0 + ar + it * 32;                                  \
                va[it] = (grow < NN)                                             \
                    ? *(const float4*)&X[(size_t)grow * DD + (k0) + ak4 * 4]     \
                    : make_float4(0.f, 0.f, 0.f, 0.f);                           \
            }                                                                    \
            _Pragma("unroll")                                                    \
            for (int it = 0; it < 2; it++)                                       \
                vb[it] = *(const float4*)&Wsrc[(size_t)((k0) + bkk + it * 16) * 64 + bj4 * 4]; \
            if (tid < 64) wvr = g_wv[2 + (tid >> 5)][(k0) + (tid & 31)];         \
        }

    #define STS_CHUNK(buf)                                                       \
        {                                                                        \
            _Pragma("unroll")                                                    \
            for (int it = 0; it < 4; it++) {                                     \
                int r = ar + it * 32;                                            \
                As[buf][ak4*4+0][r] = elu1(va[it].x);                            \
                As[buf][ak4*4+1][r] = elu1(va[it].y);                            \
                As[buf][ak4*4+2][r] = elu1(va[it].z);                            \
                As[buf][ak4*4+3][r] = elu1(va[it].w);                            \
            }                                                                    \
            _Pragma("unroll")                                                    \
            for (int it = 0; it < 2; it++)                                       \
                Bs[buf][bkk + it * 16][bj4] = vb[it];                            \
            if (tid < 64) Wch[buf][tid >> 5][tid & 31] = wvr;                    \
        }

    LDG_CHUNK(0);
    STS_CHUNK(0);
    __syncthreads();

    #pragma unroll
    for (int c = 0; c < 8; c++) {
        if (c < 7) LDG_CHUNK((c + 1) * 32);
        const int buf = c & 1;

        #pragma unroll
        for (int kk = 0; kk < 32; kk++) {
            u64 a2[4];
            #pragma unroll
            for (int q = 0; q < 2; q++) {
                ulonglong2 t = *(const ulonglong2*)&As[buf][kk][tcy * 8 + q * 4];
                a2[q*2]   = t.x;
                a2[q*2+1] = t.y;
            }
            float4 bv = Bs[buf][kk][tcx];
            u64 bb[4];
            bb[0] = pack2(bv.x, bv.x); bb[1] = pack2(bv.y, bv.y);
            bb[2] = pack2(bv.z, bv.z); bb[3] = pack2(bv.w, bv.w);
            #pragma unroll
            for (int rp = 0; rp < 4; rp++)
                #pragma unroll
                for (int j = 0; j < 4; j++)
                    acc2[rp][j] = ffma2(a2[rp], bb[j], acc2[rp][j]);
        }

        // a_d partials: threads 0..127, one (row-pair, q) each
        if (tid < 128) {
            const float* wrow = Wch[buf][aq];
            #pragma unroll
            for (int k4 = 0; k4 < 8; k4++) {
                float4 w4 = *(const float4*)&wrow[k4 * 4];
                u64 p0 = *(const u64*)&As[buf][k4*4+0][pair * 2];
                u64 p1 = *(const u64*)&As[buf][k4*4+1][pair * 2];
                u64 p2 = *(const u64*)&As[buf][k4*4+2][pair * 2];
                u64 p3 = *(const u64*)&As[buf][k4*4+3][pair * 2];
                sa2 = ffma2(p0, pack2(w4.x, w4.x), sa2);
                sa2 = ffma2(p1, pack2(w4.y, w4.y), sa2);
                sa2 = ffma2(p2, pack2(w4.z, w4.z), sa2);
                sa2 = ffma2(p3, pack2(w4.w, w4.w), sa2);
            }
        }

        if (c < 7) STS_CHUNK((c + 1) & 1);
        __syncthreads();
    }

    // epilogue: store Y; a_s from accumulators (h = tcx>>3)
    float attv[4];
    {
        int base = (tcx >> 3) * 32 + (tcx & 7) * 4;
        #pragma unroll
        for (int j = 0; j < 4; j++) attv[j] = att_src[base + j];
    }
    #pragma unroll
    for (int rp = 0; rp < 4; rp++) {
        float lo[4], hi[4];
        #pragma unroll
        for (int j = 0; j < 4; j++) unpack2(acc2[rp][j], lo[j], hi[j]);
        #pragma unroll
        for (int half = 0; half < 2; half++) {
            const float* accr = half ? hi : lo;
            int grow = row0 + tcy * 8 + rp * 2 + half;
            float part = 0.f;
            #pragma unroll
            for (int j = 0; j < 4; j++) part = fmaf(accr[j], attv[j], part);
            part += __shfl_xor_sync(0xffffffffu, part, 1);
            part += __shfl_xor_sync(0xffffffffu, part, 2);
            part += __shfl_xor_sync(0xffffffffu, part, 4);
            if (grow < NN) {
                *(float4*)&g_Y[m][grow][tcx * 4] =
                    make_float4(accr[0], accr[1], accr[2], accr[3]);
                if ((tcx & 7) == 0) g_a[m][grow][tcx >> 3] = part;
            }
        }
    }
    if (tid < 128) {
        float s0, s1;
        unpack2(sa2, s0, s1);
        int grow = row0 + pair * 2;
        if (grow < NN)     g_a[m][grow][2 + aq] = s0;
        if (grow + 1 < NN) g_a[m][grow + 1][2 + aq] = s1;
    }
    #undef LDG_CHUNK
    #undef STS_CHUNK
}

// One warp per (node, dir): gather CSR segment, fused softmax + weighted sum.
__global__ __launch_bounds__(256) void aggr_kernel(float* __restrict__ out,
                                                   const float* __restrict__ bias) {
    int warp = (blockIdx.x * 256 + threadIdx.x) >> 5;
    if (warp >= 2 * NN) return;
    int lane = threadIdx.x & 31;
    int dir = warp >= NN;
    int i = warp - dir * NN;
    int half = lane >> 4;
    int c4 = lane & 15;
    int h = (lane >> 3) & 1;
    int ms = dir, md = 1 - dir;

    float a_d = g_a[md][i][2 + h];
    float den = 0.f;
    float4 num = make_float4(0.f, 0.f, 0.f, 0.f);

    if (half == 0) {  // self loop
        float al = g_a[ms][i][h] + a_d;
        al = al > 0.f ? al : 0.2f * al;
        float ea = __expf(al);
        den = ea;
        float4 v = *(const float4*)&g_Y[ms][i][c4 * 4];
        num.x = ea * v.x; num.y = ea * v.y; num.z = ea * v.z; num.w = ea * v.w;
    }

    int beg = g_off[dir][i], end = g_off[dir][i + 1];
    for (int j = beg + half; j < end; j += 2) {
        int s = g_srcs[dir][j];
        float al = g_a[ms][s][h] + a_d;
        al = al > 0.f ? al : 0.2f * al;
        float ea = __expf(al);
        den += ea;
        float4 v = *(const float4*)&g_Y[ms][s][c4 * 4];
        num.x = fmaf(ea, v.x, num.x);
        num.y = fmaf(ea, v.y, num.y);
        num.z = fmaf(ea, v.z, num.z);
        num.w = fmaf(ea, v.w, num.w);
    }

    num.x += __shfl_xor_sync(0xffffffffu, num.x, 16);
    num.y += __shfl_xor_sync(0xffffffffu, num.y, 16);
    num.z += __shfl_xor_sync(0xffffffffu, num.z, 16);
    num.w += __shfl_xor_sync(0xffffffffu, num.w, 16);
    den   += __shfl_xor_sync(0xffffffffu, den,   16);

    if (half == 0) {
        float w = 1.f / (den + 1e-16f);
        float4 b = ((const float4*)bias)[c4];
        float4 o = make_float4(fmaf(num.x, w, b.x), fmaf(num.y, w, b.y),
                               fmaf(num.z, w, b.z), fmaf(num.w, w, b.w));
        float* dp = out + ((dir == 0) ? (size_t)NN * 64 : (size_t)0)
                        + (size_t)i * 64 + c4 * 4;
        *(float4*)dp = o;
    }
}

extern "C" void kernel_launch(void* const* d_in, const int* in_sizes, int n_in,
                              void* d_out, int out_size) {
    const float* hx      = (const float*)d_in[0];
    const float* txp     = (const float*)d_in[1];
    const void*  ei      = d_in[2];               // int32 or int64, auto-detected
    const float* Wsrc    = (const float*)d_in[3];
    const float* Wdst    = (const float*)d_in[4];
    const float* att_src = (const float*)d_in[5];
    const float* att_dst = (const float*)d_in[6];
    const float* bias    = (const float*)d_in[7];
    float* out = (float*)d_out;

    detect_kernel<<<1, 32>>>((const int*)ei);
    prep_wv_kernel<<<4, 256>>>(Wsrc, Wdst, att_src, att_dst);
    zero_kernel<<<(2 * NN + 255) / 256, 256>>>();
    gemm_kernel<<<dim3((NN + 127) / 128, 2), 256>>>(hx, txp, Wsrc, att_src, ei);
    scan1_kernel<<<dim3(NB, 2), 256>>>();
    scan2_kernel<<<2, 256>>>();
    scan3_kernel<<<dim3(NB, 2), 256>>>();
    scatter_kernel<<<(EE + 255) / 256, 256>>>(ei);
    aggr_kernel<<<(2 * NN * 32 + 255) / 256, 256>>>(out, bias);
}

// round 13
// speedup vs baseline: 1.2005x; 1.2005x over previous
#include <cuda_runtime.h>
#include <cstdint>
#include <cstddef>

#define NN 50000
#define DD 256
#define EE 1000000
#define NB 196   // ceil(NN/256)

typedef unsigned long long u64;

// ---- device scratch (no malloc allowed) ----
__device__ float g_Y[2][NN][64];    // [m: 0=h,1=t][node][src-proj 64]
__device__ float g_a[2][NN][4];     // [m][node][ a_s h0, a_s h1, a_d h0, a_d h1 ]
__device__ float g_wv[4][DD];       // folded att vectors: [kind*2+h][k]
__device__ int   g_cnt[2][NN];      // in-degree histogram per direction
__device__ int   g_off[2][NN + 1];  // CSR offsets
__device__ int   g_cur[2][NN];      // scatter cursors
__device__ int   g_srcs[2][EE];     // edge sources sorted by dst
__device__ int   g_part[2][NB];     // per-block partials for scan
__device__ int   g_is64;            // edge_index dtype flag

__device__ __forceinline__ float elu1(float x) {
    return x > 0.f ? x : expm1f(x);
}

__device__ __forceinline__ u64 pack2(float lo, float hi) {
    u64 r; asm("mov.b64 %0, {%1,%2};" : "=l"(r) : "f"(lo), "f"(hi)); return r;
}
__device__ __forceinline__ void unpack2(u64 v, float& lo, float& hi) {
    asm("mov.b64 {%0,%1}, %2;" : "=f"(lo), "=f"(hi) : "l"(v));
}
__device__ __forceinline__ u64 ffma2(u64 a, u64 b, u64 c) {
    u64 d; asm("fma.rn.f32x2 %0, %1, %2, %3;" : "=l"(d) : "l"(a), "l"(b), "l"(c));
    return d;
}

// init: zero histogram (blocks 0..390), fold att into W (blocks 391..394),
// detect edge dtype (block 394 thread 255).
__global__ __launch_bounds__(256) void init_kernel(
    const float* __restrict__ Wsrc, const float* __restrict__ Wdst,
    const float* __restrict__ att_src, const float* __restrict__ att_dst,
    const int* __restrict__ ei32)
{
    int b = blockIdx.x;
    if (b < 391) {
        int i = b * 256 + threadIdx.x;
        if (i < 2 * NN) ((int*)g_cnt)[i] = 0;
    } else if (b < 395) {
        int idx = (b - 391) * 256 + threadIdx.x;   // 0..1023
        int q = idx >> 8;          // kind*2+h
        int k = idx & 255;
        int kind = q >> 1, h = q & 1;
        const float* W = kind ? Wdst : Wsrc;
        const float* att = kind ? att_dst : att_src;
        float s = 0.f;
        #pragma unroll
        for (int c = 0; c < 32; c++)
            s = fmaf(W[k * 64 + h * 32 + c], att[h * 32 + c], s);
        g_wv[q][k] = s;
        if (b == 394 && threadIdx.x == 255) {
            int z = ei32[1] | ei32[3] | ei32[5] | ei32[7] | ei32[9] | ei32[11] | ei32[13];
            g_is64 = (z == 0) ? 1 : 0;
            g_off[0][NN] = EE;
            g_off[1][NN] = EE;
        }
    }
}

__device__ __forceinline__ void load_edge(const void* eiv, int e, int& a, int& b) {
    if (g_is64) {
        const long long* ei = (const long long*)eiv;
        a = (int)__ldg(&ei[e]); b = (int)__ldg(&ei[EE + e]);
    } else {
        const int* ei = (const int*)eiv;
        a = __ldg(&ei[e]); b = __ldg(&ei[EE + e]);
    }
}

// exclusive block scan helper (256 threads)
__device__ __forceinline__ int block_exscan(int v, int* tot) {
    int lane = threadIdx.x & 31, wid = threadIdx.x >> 5;
    int inc = v;
    #pragma unroll
    for (int o = 1; o < 32; o <<= 1) {
        int n = __shfl_up_sync(0xffffffffu, inc, o);
        if (lane >= o) inc += n;
    }
    __shared__ int ws[8];
    if (lane == 31) ws[wid] = inc;
    __syncthreads();
    if (wid == 0) {
        int w = (lane < 8) ? ws[lane] : 0;
        #pragma unroll
        for (int o = 1; o < 8; o <<= 1) {
            int n = __shfl_up_sync(0xffffffffu, w, o);
            if (lane >= o) w += n;
        }
        if (lane < 8) ws[lane] = w;
    }
    __syncthreads();
    int base = (wid > 0) ? ws[wid - 1] : 0;
    *tot = ws[7];
    return base + inc - v;
}

__global__ __launch_bounds__(256) void scan1_kernel() {
    int dir = blockIdx.y;
    int idx = blockIdx.x * 256 + threadIdx.x;
    int c = (idx < NN) ? g_cnt[dir][idx] : 0;
    int tot;
    block_exscan(c, &tot);
    if (threadIdx.x == 0) g_part[dir][blockIdx.x] = tot;
}

__global__ __launch_bounds__(256) void scan2_kernel() {
    int dir = blockIdx.x;
    int v = (threadIdx.x < NB) ? g_part[dir][threadIdx.x] : 0;
    int tot;
    int ex = block_exscan(v, &tot);
    if (threadIdx.x < NB) g_part[dir][threadIdx.x] = ex;
}

__global__ __launch_bounds__(256) void scan3_kernel() {
    int dir = blockIdx.y;
    int idx = blockIdx.x * 256 + threadIdx.x;
    int c = (idx < NN) ? g_cnt[dir][idx] : 0;
    int tot;
    int ex = block_exscan(c, &tot) + g_part[dir][blockIdx.x];
    if (idx < NN) {
        g_off[dir][idx] = ex;
        g_cur[dir][idx] = ex;
    }
}

__global__ __launch_bounds__(256) void scatter_kernel(const void* __restrict__ eiv) {
    int e = blockIdx.x * blockDim.x + threadIdx.x;
    if (e >= EE) return;
    int a, b;
    load_edge(eiv, e, a, b);
    int p0 = atomicAdd(&g_cur[0][b], 1);
    g_srcs[0][p0] = a;
    int p1 = atomicAdd(&g_cur[1][a], 1);
    g_srcs[1][p1] = b;
}

// Y[m] = elu(X_m) @ W_src (M=50000, N=64, K=256).
// Block tile 128x64, thread tile 8x4 (f32x2 row-pairs), single-buffered (R11).
// Prologue: fire-and-forget histogram REDs overlapped with the GEMM.
// a_s from accumulators in the epilogue; a_d via packed smem loop.
__global__ __launch_bounds__(256, 3) void gemm_kernel(
    const float* __restrict__ hx, const float* __restrict__ txp,
    const float* __restrict__ Wsrc, const float* __restrict__ att_src,
    const void* __restrict__ eiv)
{
    const int m = blockIdx.y;
    const float* __restrict__ X = (m == 0) ? hx : txp;
    __shared__ __align__(16) float As[32][132];   // [k][row], 528B stride
    __shared__ float4 Bs[32][16];                 // [k][col4] (64 cols)
    __shared__ float  Wch[2][32];                 // wv[2],wv[3] chunk
    const int tid = threadIdx.x;
    const int tcx = tid & 15, tcy = tid >> 4;
    const int row0 = blockIdx.x * 128;
    const int pair = tid & 63, aq = tid >> 6;     // a_d assignment (tid<128)

    // ---- histogram slice: fire-and-forget REDs, hidden under GEMM ----
    {
        int bid = blockIdx.y * gridDim.x + blockIdx.x;   // 0..781
        int base = bid * 1280;
        #pragma unroll
        for (int t = 0; t < 5; t++) {
            int e = base + tid + t * 256;
            if (e < EE) {
                int a, b;
                load_edge(eiv, e, a, b);
                atomicAdd(&g_cnt[0][b], 1);
                atomicAdd(&g_cnt[1][a], 1);
            }
        }
    }

    u64 acc2[4][4];       // [row-pair][col]
    #pragma unroll
    for (int rp = 0; rp < 4; rp++)
        #pragma unroll
        for (int j = 0; j < 4; j++) acc2[rp][j] = 0ull;
    u64 sa2 = 0ull;       // packed a_d partials for (row-pair, q)

    for (int k0 = 0; k0 < DD; k0 += 32) {
        // A tile: 128 rows x 32 k (1024 float4, 4 per thread)
        #pragma unroll
        for (int it = 0; it < 4; it++) {
            int l = tid + 256 * it;
            int r = l >> 3, k4 = l & 7;
            int grow = row0 + r;
            float4 v = make_float4(0.f, 0.f, 0.f, 0.f);
            if (grow < NN) v = *(const float4*)&X[(size_t)grow * DD + k0 + k4 * 4];
            As[k4*4+0][r] = elu1(v.x);
            As[k4*4+1][r] = elu1(v.y);
            As[k4*4+2][r] = elu1(v.z);
            As[k4*4+3][r] = elu1(v.w);
        }
        // B tile: 32 k x 64 cols (512 float4, 2 per thread)
        #pragma unroll
        for (int it = 0; it < 2; it++) {
            int l = tid + 256 * it;
            int kk = l >> 4, j4 = l & 15;
            Bs[kk][j4] = *(const float4*)&Wsrc[(size_t)(k0 + kk) * 64 + j4 * 4];
        }
        // wv chunk for q=2,3
        if (tid < 64) Wch[tid >> 5][tid & 31] = g_wv[2 + (tid >> 5)][k0 + (tid & 31)];
        __syncthreads();

        #pragma unroll
        for (int kk = 0; kk < 32; kk++) {
            u64 a2[4];
            #pragma unroll
            for (int q = 0; q < 2; q++) {
                ulonglong2 t = *(const ulonglong2*)&As[kk][tcy * 8 + q * 4];
                a2[q*2]   = t.x;
                a2[q*2+1] = t.y;
            }
            float4 bv = Bs[kk][tcx];
            u64 bb[4];
            bb[0] = pack2(bv.x, bv.x); bb[1] = pack2(bv.y, bv.y);
            bb[2] = pack2(bv.z, bv.z); bb[3] = pack2(bv.w, bv.w);
            #pragma unroll
            for (int rp = 0; rp < 4; rp++)
                #pragma unroll
                for (int j = 0; j < 4; j++)
                    acc2[rp][j] = ffma2(a2[rp], bb[j], acc2[rp][j]);
        }

        // a_d partials: threads 0..127, one (row-pair, q) each
        if (tid < 128) {
            const float* wrow = Wch[aq];
            #pragma unroll
            for (int k4 = 0; k4 < 8; k4++) {
                float4 w4 = *(const float4*)&wrow[k4 * 4];
                u64 p0 = *(const u64*)&As[k4*4+0][pair * 2];
                u64 p1 = *(const u64*)&As[k4*4+1][pair * 2];
                u64 p2 = *(const u64*)&As[k4*4+2][pair * 2];
                u64 p3 = *(const u64*)&As[k4*4+3][pair * 2];
                sa2 = ffma2(p0, pack2(w4.x, w4.x), sa2);
                sa2 = ffma2(p1, pack2(w4.y, w4.y), sa2);
                sa2 = ffma2(p2, pack2(w4.z, w4.z), sa2);
                sa2 = ffma2(p3, pack2(w4.w, w4.w), sa2);
            }
        }
        __syncthreads();
    }

    // epilogue: store Y; a_s from accumulators (h = tcx>>3)
    float attv[4];
    {
        int base = (tcx >> 3) * 32 + (tcx & 7) * 4;
        #pragma unroll
        for (int j = 0; j < 4; j++) attv[j] = att_src[base + j];
    }
    #pragma unroll
    for (int rp = 0; rp < 4; rp++) {
        float lo[4], hi[4];
        #pragma unroll
        for (int j = 0; j < 4; j++) unpack2(acc2[rp][j], lo[j], hi[j]);
        #pragma unroll
        for (int half = 0; half < 2; half++) {
            const float* accr = half ? hi : lo;
            int grow = row0 + tcy * 8 + rp * 2 + half;
            float part = 0.f;
            #pragma unroll
            for (int j = 0; j < 4; j++) part = fmaf(accr[j], attv[j], part);
            part += __shfl_xor_sync(0xffffffffu, part, 1);
            part += __shfl_xor_sync(0xffffffffu, part, 2);
            part += __shfl_xor_sync(0xffffffffu, part, 4);
            if (grow < NN) {
                *(float4*)&g_Y[m][grow][tcx * 4] =
                    make_float4(accr[0], accr[1], accr[2], accr[3]);
                if ((tcx & 7) == 0) g_a[m][grow][tcx >> 3] = part;
            }
        }
    }
    // a_d stores
    if (tid < 128) {
        float s0, s1;
        unpack2(sa2, s0, s1);
        int grow = row0 + pair * 2;
        if (grow < NN)     g_a[m][grow][2 + aq] = s0;
        if (grow + 1 < NN) g_a[m][grow + 1][2 + aq] = s1;
    }
}

// One warp per (node, dir): gather CSR segment, fused softmax + weighted sum.
__global__ __launch_bounds__(256) void aggr_kernel(float* __restrict__ out,
                                                   const float* __restrict__ bias) {
    int warp = (blockIdx.x * 256 + threadIdx.x) >> 5;
    if (warp >= 2 * NN) return;
    int lane = threadIdx.x & 31;
    int dir = warp >= NN;
    int i = warp - dir * NN;
    int half = lane >> 4;
    int c4 = lane & 15;
    int h = (lane >> 3) & 1;
    int ms = dir, md = 1 - dir;

    float a_d = g_a[md][i][2 + h];
    float den = 0.f;
    float4 num = make_float4(0.f, 0.f, 0.f, 0.f);

    if (half == 0) {  // self loop
        float al = g_a[ms][i][h] + a_d;
        al = al > 0.f ? al : 0.2f * al;
        float ea = __expf(al);
        den = ea;
        float4 v = *(const float4*)&g_Y[ms][i][c4 * 4];
        num.x = ea * v.x; num.y = ea * v.y; num.z = ea * v.z; num.w = ea * v.w;
    }

    int beg = g_off[dir][i], end = g_off[dir][i + 1];
    for (int j = beg + half; j < end; j += 2) {
        int s = g_srcs[dir][j];
        float al = g_a[ms][s][h] + a_d;
        al = al > 0.f ? al : 0.2f * al;
        float ea = __expf(al);
        den += ea;
        float4 v = *(const float4*)&g_Y[ms][s][c4 * 4];
        num.x = fmaf(ea, v.x, num.x);
        num.y = fmaf(ea, v.y, num.y);
        num.z = fmaf(ea, v.z, num.z);
        num.w = fmaf(ea, v.w, num.w);
    }

    num.x += __shfl_xor_sync(0xffffffffu, num.x, 16);
    num.y += __shfl_xor_sync(0xffffffffu, num.y, 16);
    num.z += __shfl_xor_sync(0xffffffffu, num.z, 16);
    num.w += __shfl_xor_sync(0xffffffffu, num.w, 16);
    den   += __shfl_xor_sync(0xffffffffu, den,   16);

    if (half == 0) {
        float w = 1.f / (den + 1e-16f);
        float4 b = ((const float4*)bias)[c4];
        float4 o = make_float4(fmaf(num.x, w, b.x), fmaf(num.y, w, b.y),
                               fmaf(num.z, w, b.z), fmaf(num.w, w, b.w));
        float* dp = out + ((dir == 0) ? (size_t)NN * 64 : (size_t)0)
                        + (size_t)i * 64 + c4 * 4;
        *(float4*)dp = o;
    }
}

extern "C" void kernel_launch(void* const* d_in, const int* in_sizes, int n_in,
                              void* d_out, int out_size) {
    const float* hx      = (const float*)d_in[0];
    const float* txp     = (const float*)d_in[1];
    const void*  ei      = d_in[2];               // int32 or int64, auto-detected
    const float* Wsrc    = (const float*)d_in[3];
    const float* Wdst    = (const float*)d_in[4];
    const float* att_src = (const float*)d_in[5];
    const float* att_dst = (const float*)d_in[6];
    const float* bias    = (const float*)d_in[7];
    float* out = (float*)d_out;

    init_kernel<<<395, 256>>>(Wsrc, Wdst, att_src, att_dst, (const int*)ei);
    gemm_kernel<<<dim3((NN + 127) / 128, 2), 256>>>(hx, txp, Wsrc, att_src, ei);
    scan1_kernel<<<dim3(NB, 2), 256>>>();
    scan2_kernel<<<2, 256>>>();
    scan3_kernel<<<dim3(NB, 2), 256>>>();
    scatter_kernel<<<(EE + 255) / 256, 256>>>(ei);
    aggr_kernel<<<(2 * NN * 32 + 255) / 256, 256>>>(out, bias);
}

// round 14
// speedup vs baseline: 1.2566x; 1.0467x over previous
#include <cuda_runtime.h>
#include <mma.h>
#include <cstdint>
#include <cstddef>

#define NN 50000
#define NNP 50048   // padded rows for boundary-block wmma stores
#define DD 256
#define EE 1000000
#define NB 196   // ceil(NN/256)

typedef unsigned long long u64;
using namespace nvcuda;

// ---- device scratch (no malloc allowed) ----
__device__ float g_Y[2][NNP][64];   // [m: 0=h,1=t][node][src-proj 64]
__device__ float g_a[2][NN][4];     // [m][node][ a_s h0, a_s h1, a_d h0, a_d h1 ]
__device__ float g_wv[4][DD];       // folded att vectors: [kind*2+h][k]
__device__ int   g_cnt[2][NN];      // in-degree histogram per direction
__device__ int   g_off[2][NN + 1];  // CSR offsets
__device__ int   g_cur[2][NN];      // scatter cursors
__device__ int   g_srcs[2][EE];     // edge sources sorted by dst
__device__ int   g_part[2][NB];     // per-block partials for scan
__device__ int   g_is64;            // edge_index dtype flag

__device__ __forceinline__ float elu1(float x) {
    return x > 0.f ? x : expm1f(x);
}

// init: zero histogram (blocks 0..390), fold att into W (blocks 391..394),
// detect edge dtype (block 394 thread 255).
__global__ __launch_bounds__(256) void init_kernel(
    const float* __restrict__ Wsrc, const float* __restrict__ Wdst,
    const float* __restrict__ att_src, const float* __restrict__ att_dst,
    const int* __restrict__ ei32)
{
    int b = blockIdx.x;
    if (b < 391) {
        int i = b * 256 + threadIdx.x;
        if (i < 2 * NN) ((int*)g_cnt)[i] = 0;
    } else if (b < 395) {
        int idx = (b - 391) * 256 + threadIdx.x;   // 0..1023
        int q = idx >> 8;          // kind*2+h
        int k = idx & 255;
        int kind = q >> 1, h = q & 1;
        const float* W = kind ? Wdst : Wsrc;
        const float* att = kind ? att_dst : att_src;
        float s = 0.f;
        #pragma unroll
        for (int c = 0; c < 32; c++)
            s = fmaf(W[k * 64 + h * 32 + c], att[h * 32 + c], s);
        g_wv[q][k] = s;
        if (b == 394 && threadIdx.x == 255) {
            int z = ei32[1] | ei32[3] | ei32[5] | ei32[7] | ei32[9] | ei32[11] | ei32[13];
            g_is64 = (z == 0) ? 1 : 0;
            g_off[0][NN] = EE;
            g_off[1][NN] = EE;
        }
    }
}

__device__ __forceinline__ void load_edge(const void* eiv, int e, int& a, int& b) {
    if (g_is64) {
        const long long* ei = (const long long*)eiv;
        a = (int)__ldg(&ei[e]); b = (int)__ldg(&ei[EE + e]);
    } else {
        const int* ei = (const int*)eiv;
        a = __ldg(&ei[e]); b = __ldg(&ei[EE + e]);
    }
}

// exclusive block scan helper (256 threads)
__device__ __forceinline__ int block_exscan(int v, int* tot) {
    int lane = threadIdx.x & 31, wid = threadIdx.x >> 5;
    int inc = v;
    #pragma unroll
    for (int o = 1; o < 32; o <<= 1) {
        int n = __shfl_up_sync(0xffffffffu, inc, o);
        if (lane >= o) inc += n;
    }
    __shared__ int ws[8];
    if (lane == 31) ws[wid] = inc;
    __syncthreads();
    if (wid == 0) {
        int w = (lane < 8) ? ws[lane] : 0;
        #pragma unroll
        for (int o = 1; o < 8; o <<= 1) {
            int n = __shfl_up_sync(0xffffffffu, w, o);
            if (lane >= o) w += n;
        }
        if (lane < 8) ws[lane] = w;
    }
    __syncthreads();
    int base = (wid > 0) ? ws[wid - 1] : 0;
    *tot = ws[7];
    return base + inc - v;
}

__global__ __launch_bounds__(256) void scan1_kernel() {
    int dir = blockIdx.y;
    int idx = blockIdx.x * 256 + threadIdx.x;
    int c = (idx < NN) ? g_cnt[dir][idx] : 0;
    int tot;
    block_exscan(c, &tot);
    if (threadIdx.x == 0) g_part[dir][blockIdx.x] = tot;
}

__global__ __launch_bounds__(256) void scan2_kernel() {
    int dir = blockIdx.x;
    int v = (threadIdx.x < NB) ? g_part[dir][threadIdx.x] : 0;
    int tot;
    int ex = block_exscan(v, &tot);
    if (threadIdx.x < NB) g_part[dir][threadIdx.x] = ex;
}

__global__ __launch_bounds__(256) void scan3_kernel() {
    int dir = blockIdx.y;
    int idx = blockIdx.x * 256 + threadIdx.x;
    int c = (idx < NN) ? g_cnt[dir][idx] : 0;
    int tot;
    int ex = block_exscan(c, &tot) + g_part[dir][blockIdx.x];
    if (idx < NN) {
        g_off[dir][idx] = ex;
        g_cur[dir][idx] = ex;
    }
}

__global__ __launch_bounds__(256) void scatter_kernel(const void* __restrict__ eiv) {
    int e = blockIdx.x * blockDim.x + threadIdx.x;
    if (e >= EE) return;
    int a, b;
    load_edge(eiv, e, a, b);
    int p0 = atomicAdd(&g_cur[0][b], 1);
    g_srcs[0][p0] = a;
    int p1 = atomicAdd(&g_cur[1][a], 1);
    g_srcs[1][p1] = b;
}

// Y[m] = elu(X_m) @ W_src via tf32 WMMA (m16n16k8), block tile 64x64, 8 warps.
// As row-major -> all 4 per-node logits from a uniform float4 smem loop.
// Prologue: fire-and-forget histogram REDs overlapped with the GEMM.
__global__ __launch_bounds__(256) void gemm_kernel(
    const float* __restrict__ hx, const float* __restrict__ txp,
    const float* __restrict__ Wsrc, const void* __restrict__ eiv)
{
    const int m = blockIdx.y;
    const float* __restrict__ X = (m == 0) ? hx : txp;
    __shared__ __align__(16) float As[64][36];   // [row][k], ld=36
    __shared__ __align__(16) float Bs[32][68];   // [k][col], ld=68
    __shared__ float Wch[4][32];                 // wv chunk [q][kk]
    const int tid = threadIdx.x;
    const int w = tid >> 5;                      // warp 0..7
    const int wm = w & 3, wn = w >> 2;           // frag grid 4x2
    const int row0 = blockIdx.x * 64;
    const int lrow = tid & 63, lq = tid >> 6;    // logit assignment

    // ---- histogram slice: fire-and-forget REDs, hidden under GEMM ----
    {
        int bid = blockIdx.y * gridDim.x + blockIdx.x;   // 0..1563
        int base = bid * 640;
        #pragma unroll
        for (int t = 0; t < 3; t++) {
            int off = tid + t * 256;
            int e = base + off;
            if (off < 640 && e < EE) {
                int a, b;
                load_edge(eiv, e, a, b);
                atomicAdd(&g_cnt[0][b], 1);
                atomicAdd(&g_cnt[1][a], 1);
            }
        }
    }

    wmma::fragment<wmma::accumulator, 16, 16, 8, float> fc0, fc1;
    wmma::fill_fragment(fc0, 0.f);
    wmma::fill_fragment(fc1, 0.f);
    float4 sa = make_float4(0.f, 0.f, 0.f, 0.f);   // logit partial (x used)
    float salog = 0.f;

    for (int k0 = 0; k0 < DD; k0 += 32) {
        // A tile: 64 rows x 32 k (512 float4, 2 per thread), row-major
        #pragma unroll
        for (int it = 0; it < 2; it++) {
            int l = tid + 256 * it;
            int r = l >> 3, k4 = l & 7;
            int grow = row0 + r;
            float4 v = make_float4(0.f, 0.f, 0.f, 0.f);
            if (grow < NN) v = *(const float4*)&X[(size_t)grow * DD + k0 + k4 * 4];
            v.x = elu1(v.x); v.y = elu1(v.y); v.z = elu1(v.z); v.w = elu1(v.w);
            *(float4*)&As[r][k4 * 4] = v;
        }
        // B tile: 32 k x 64 cols (512 float4, 2 per thread), row-major
        #pragma unroll
        for (int it = 0; it < 2; it++) {
            int l = tid + 256 * it;
            int kk = l >> 4, j4 = l & 15;
            *(float4*)&Bs[kk][j4 * 4] =
                *(const float4*)&Wsrc[(size_t)(k0 + kk) * 64 + j4 * 4];
        }
        // wv chunk: 4 q x 32 k
        if (tid < 128) Wch[tid >> 5][tid & 31] = g_wv[tid >> 5][k0 + (tid & 31)];
        __syncthreads();

        // tensor-core MMAs
        #pragma unroll
        for (int ks = 0; ks < 4; ks++) {
            wmma::fragment<wmma::matrix_a, 16, 16, 8, wmma::precision::tf32,
                           wmma::row_major> fa;
            wmma::fragment<wmma::matrix_b, 16, 16, 8, wmma::precision::tf32,
                           wmma::row_major> fb0, fb1;
            wmma::load_matrix_sync(fa, &As[wm * 16][ks * 8], 36);
            wmma::load_matrix_sync(fb0, &Bs[ks * 8][wn * 32], 68);
            wmma::load_matrix_sync(fb1, &Bs[ks * 8][wn * 32 + 16], 68);
            #pragma unroll
            for (int i = 0; i < fa.num_elements; i++)
                fa.x[i] = wmma::__float_to_tf32(fa.x[i]);
            #pragma unroll
            for (int i = 0; i < fb0.num_elements; i++) {
                fb0.x[i] = wmma::__float_to_tf32(fb0.x[i]);
                fb1.x[i] = wmma::__float_to_tf32(fb1.x[i]);
            }
            wmma::mma_sync(fc0, fa, fb0, fc0);
            wmma::mma_sync(fc1, fa, fb1, fc1);
        }

        // logit partial: thread (lrow, lq), fp32 float4 dot over this chunk
        {
            const float* wrow = Wch[lq];
            #pragma unroll
            for (int k4 = 0; k4 < 8; k4++) {
                float4 a4 = *(const float4*)&As[lrow][k4 * 4];
                float4 w4 = *(const float4*)&wrow[k4 * 4];
                salog = fmaf(a4.x, w4.x, salog);
                salog = fmaf(a4.y, w4.y, salog);
                salog = fmaf(a4.z, w4.z, salog);
                salog = fmaf(a4.w, w4.w, salog);
            }
        }
        __syncthreads();
    }

    // store Y tile (g_Y padded to NNP rows; OOB rows never read)
    wmma::store_matrix_sync(&g_Y[m][row0 + wm * 16][wn * 32], fc0, 64,
                            wmma::mem_row_major);
    wmma::store_matrix_sync(&g_Y[m][row0 + wm * 16][wn * 32 + 16], fc1, 64,
                            wmma::mem_row_major);
    if (row0 + lrow < NN) g_a[m][row0 + lrow][lq] = salog;
    (void)sa;
}

// One warp per (node, dir): gather CSR segment, fused softmax + weighted sum.
__global__ __launch_bounds__(256) void aggr_kernel(float* __restrict__ out,
                                                   const float* __restrict__ bias) {
    int warp = (blockIdx.x * 256 + threadIdx.x) >> 5;
    if (warp >= 2 * NN) return;
    int lane = threadIdx.x & 31;
    int dir = warp >= NN;
    int i = warp - dir * NN;
    int half = lane >> 4;
    int c4 = lane & 15;
    int h = (lane >> 3) & 1;
    int ms = dir, md = 1 - dir;

    float a_d = g_a[md][i][2 + h];
    float den = 0.f;
    float4 num = make_float4(0.f, 0.f, 0.f, 0.f);

    if (half == 0) {  // self loop
        float al = g_a[ms][i][h] + a_d;
        al = al > 0.f ? al : 0.2f * al;
        float ea = __expf(al);
        den = ea;
        float4 v = *(const float4*)&g_Y[ms][i][c4 * 4];
        num.x = ea * v.x; num.y = ea * v.y; num.z = ea * v.z; num.w = ea * v.w;
    }

    int beg = g_off[dir][i], end = g_off[dir][i + 1];
    for (int j = beg + half; j < end; j += 2) {
        int s = g_srcs[dir][j];
        float al = g_a[ms][s][h] + a_d;
        al = al > 0.f ? al : 0.2f * al;
        float ea = __expf(al);
        den += ea;
        float4 v = *(const float4*)&g_Y[ms][s][c4 * 4];
        num.x = fmaf(ea, v.x, num.x);
        num.y = fmaf(ea, v.y, num.y);
        num.z = fmaf(ea, v.z, num.z);
        num.w = fmaf(ea, v.w, num.w);
    }

    num.x += __shfl_xor_sync(0xffffffffu, num.x, 16);
    num.y += __shfl_xor_sync(0xffffffffu, num.y, 16);
    num.z += __shfl_xor_sync(0xffffffffu, num.z, 16);
    num.w += __shfl_xor_sync(0xffffffffu, num.w, 16);
    den   += __shfl_xor_sync(0xffffffffu, den,   16);

    if (half == 0) {
        float w = 1.f / (den + 1e-16f);
        float4 b = ((const float4*)bias)[c4];
        float4 o = make_float4(fmaf(num.x, w, b.x), fmaf(num.y, w, b.y),
                               fmaf(num.z, w, b.z), fmaf(num.w, w, b.w));
        float* dp = out + ((dir == 0) ? (size_t)NN * 64 : (size_t)0)
                        + (size_t)i * 64 + c4 * 4;
        *(float4*)dp = o;
    }
}

extern "C" void kernel_launch(void* const* d_in, const int* in_sizes, int n_in,
                              void* d_out, int out_size) {
    const float* hx      = (const float*)d_in[0];
    const float* txp     = (const float*)d_in[1];
    const void*  ei      = d_in[2];               // int32 or int64, auto-detected
    const float* Wsrc    = (const float*)d_in[3];
    const float* Wdst    = (const float*)d_in[4];
    const float* att_src = (const float*)d_in[5];
    const float* att_dst = (const float*)d_in[6];
    const float* bias    = (const float*)d_in[7];
    float* out = (float*)d_out;

    init_kernel<<<395, 256>>>(Wsrc, Wdst, att_src, att_dst, (const int*)ei);
    gemm_kernel<<<dim3((NN + 63) / 64, 2), 256>>>(hx, txp, Wsrc, ei);
    scan1_kernel<<<dim3(NB, 2), 256>>>();
    scan2_kernel<<<2, 256>>>();
    scan3_kernel<<<dim3(NB, 2), 256>>>();
    scatter_kernel<<<(EE + 255) / 256, 256>>>(ei);
    aggr_kernel<<<(2 * NN * 32 + 255) / 256, 256>>>(out, bias);
}